// round 1
// baseline (speedup 1.0000x reference)
#include <cuda_runtime.h>
#include <math.h>

#define MAXN 100000
#define MAXE 1600000
#define FD   128      // IN == HID == 128
#define OUTC 64

// ---------------- scratch (device globals; no allocation allowed) ----------
__device__ float g_bufA[MAXN * FD];   // agg outputs
__device__ float g_bufB[MAXN * FD];   // gemm outputs
__device__ int   g_cnt[MAXN];
__device__ int   g_rowptr[MAXN + 1];
__device__ int   g_cursor[MAXN];
__device__ int   g_csr[MAXE];
__device__ float g_dinv[MAXN];
__device__ int   g_bsums[256];

// ---------------- degree / CSR build ---------------------------------------
__global__ void k_zero_cnt(int n) {
    int i = blockIdx.x * blockDim.x + threadIdx.x;
    if (i < n) g_cnt[i] = 0;
}

__global__ void k_count(const int* __restrict__ ei, int e) {
    int i = blockIdx.x * blockDim.x + threadIdx.x;
    if (i < e) atomicAdd(&g_cnt[ei[e + i]], 1);   // ei[1][i] = dst
}

// block-level scan: 256 threads x 4 items = 1024/block.
// writes inclusive-within-block prefix into g_cursor, block total into g_bsums.
__global__ void k_scan1(int n) {
    int tid = threadIdx.x, lane = tid & 31, w = tid >> 5;
    int base = blockIdx.x * 1024 + tid * 4;
    int v[4], inc[4];
    int s = 0;
#pragma unroll
    for (int j = 0; j < 4; j++) {
        v[j] = (base + j < n) ? g_cnt[base + j] : 0;
        s += v[j];
        inc[j] = s;
    }
    // warp inclusive scan of per-thread sums
    int x = s;
#pragma unroll
    for (int o = 1; o < 32; o <<= 1) {
        int t = __shfl_up_sync(0xFFFFFFFFu, x, o);
        if (lane >= o) x += t;
    }
    __shared__ int wsum[8], woff[8];
    if (lane == 31) wsum[w] = x;
    __syncthreads();
    if (tid < 8) {
        int ws = wsum[tid];
        int y = ws;
#pragma unroll
        for (int o = 1; o < 8; o <<= 1) {
            int t = __shfl_up_sync(0xFFu, y, o);
            if (tid >= o) y += t;
        }
        woff[tid] = y - ws;
        if (tid == 7) g_bsums[blockIdx.x] = y;
    }
    __syncthreads();
    int thread_excl = woff[w] + x - s;
#pragma unroll
    for (int j = 0; j < 4; j++)
        if (base + j < n) g_cursor[base + j] = thread_excl + inc[j];
}

// single-block exclusive scan of block sums (nb <= 256)
__global__ void k_scan2(int nb) {
    int tid = threadIdx.x, lane = tid & 31, w = tid >> 5;
    int v = (tid < nb) ? g_bsums[tid] : 0;
    int x = v;
#pragma unroll
    for (int o = 1; o < 32; o <<= 1) {
        int t = __shfl_up_sync(0xFFFFFFFFu, x, o);
        if (lane >= o) x += t;
    }
    __shared__ int wsum[8], woff[8];
    if (lane == 31) wsum[w] = x;
    __syncthreads();
    if (tid < 8) {
        int ws = wsum[tid];
        int y = ws;
#pragma unroll
        for (int o = 1; o < 8; o <<= 1) {
            int t = __shfl_up_sync(0xFFu, y, o);
            if (tid >= o) y += t;
        }
        woff[tid] = y - ws;
    }
    __syncthreads();
    int incl = woff[w] + x;
    if (tid < nb) g_bsums[tid] = incl - v;   // exclusive
}

__global__ void k_final(int n) {
    int i = blockIdx.x * blockDim.x + threadIdx.x;
    if (i >= n) return;
    int incl = g_cursor[i] + g_bsums[i >> 10];
    int c = g_cnt[i];
    int excl = incl - c;
    g_rowptr[i] = excl;
    g_cursor[i] = excl;
    g_dinv[i] = rsqrtf((float)c + 1.0f);   // deg = in-degree + self loop
    if (i == n - 1) g_rowptr[n] = incl;
}

__global__ void k_fill(const int* __restrict__ ei, int e) {
    int i = blockIdx.x * blockDim.x + threadIdx.x;
    if (i < e) {
        int d = ei[e + i];
        int p = atomicAdd(&g_cursor[d], 1);
        g_csr[p] = ei[i];                  // src
    }
}

// ---------------- normalized aggregation: Y = D^-1/2 (A+I) D^-1/2 X --------
// one warp per node, float4 per lane (F=128 -> 512B row, one coalesced load)
__global__ void k_agg(const float* __restrict__ X, float* __restrict__ Y, int n) {
    int gw = (blockIdx.x * blockDim.x + threadIdx.x) >> 5;
    int lane = threadIdx.x & 31;
    if (gw >= n) return;
    float di = g_dinv[gw];
    const float4* x4 = (const float4*)X;

    float4 a = __ldg(&x4[(size_t)gw * 32 + lane]);
    float4 acc = make_float4(di * a.x, di * a.y, di * a.z, di * a.w);  // self loop (pre-final-scale)

    int s0 = g_rowptr[gw], s1 = g_rowptr[gw + 1];
    int e = s0;
    for (; e + 1 < s1; e += 2) {
        int sA = __ldg(&g_csr[e]);
        int sB = __ldg(&g_csr[e + 1]);
        float wA = __ldg(&g_dinv[sA]);
        float wB = __ldg(&g_dinv[sB]);
        float4 vA = __ldg(&x4[(size_t)sA * 32 + lane]);
        float4 vB = __ldg(&x4[(size_t)sB * 32 + lane]);
        acc.x += wA * vA.x + wB * vB.x;
        acc.y += wA * vA.y + wB * vB.y;
        acc.z += wA * vA.z + wB * vB.z;
        acc.w += wA * vA.w + wB * vB.w;
    }
    if (e < s1) {
        int sA = __ldg(&g_csr[e]);
        float wA = __ldg(&g_dinv[sA]);
        float4 vA = __ldg(&x4[(size_t)sA * 32 + lane]);
        acc.x += wA * vA.x; acc.y += wA * vA.y;
        acc.z += wA * vA.z; acc.w += wA * vA.w;
    }
    float4 o = make_float4(di * acc.x, di * acc.y, di * acc.z, di * acc.w);
    ((float4*)Y)[(size_t)gw * 32 + lane] = o;
}

// ---------------- fp32 GEMM: C[n,128] = A[n,128] @ [Wa|Wb](128x128) + bias --
// block: 256 threads, 64-row tile; thread = (tx 0..31 cols, ty 0..7 row grp),
// 8 rows x 4 cols accumulators.
__global__ void k_gemm(const float* __restrict__ A,
                       const float* __restrict__ Wa, int Na,
                       const float* __restrict__ Wb,
                       const float* __restrict__ ba, const float* __restrict__ bb,
                       float* __restrict__ C, int n) {
    extern __shared__ float sm[];
    float* Ws = sm;                 // 128*128
    float* As = sm + 128 * 128;     // 64*128
    float* Bs = As + 64 * 128;      // 128
    int tid = threadIdx.x;
    int Nb = 128 - Na;

    for (int idx = tid; idx < 128 * 128; idx += 256) {
        int k = idx >> 7, c = idx & 127;
        Ws[idx] = (c < Na) ? __ldg(&Wa[k * Na + c]) : __ldg(&Wb[k * Nb + (c - Na)]);
    }
    if (tid < 128) Bs[tid] = (tid < Na) ? __ldg(&ba[tid]) : __ldg(&bb[tid - Na]);

    int row0 = blockIdx.x * 64;
    for (int t = tid * 4; t < 64 * 128; t += 1024) {
        int r = t >> 7, c = t & 127;
        int gr = row0 + r;
        float4 v = make_float4(0.f, 0.f, 0.f, 0.f);
        if (gr < n) v = *(const float4*)&A[(size_t)gr * 128 + c];
        *(float4*)&As[t] = v;
    }
    __syncthreads();

    int tx = tid & 31, ty = tid >> 5;
    float acc[8][4];
#pragma unroll
    for (int r = 0; r < 8; r++)
#pragma unroll
        for (int c = 0; c < 4; c++) acc[r][c] = 0.f;

#pragma unroll 4
    for (int k = 0; k < 128; k++) {
        float4 w = *(float4*)&Ws[k * 128 + tx * 4];
#pragma unroll
        for (int r = 0; r < 8; r++) {
            float av = As[(ty * 8 + r) * 128 + k];   // warp-uniform broadcast
            acc[r][0] += av * w.x;
            acc[r][1] += av * w.y;
            acc[r][2] += av * w.z;
            acc[r][3] += av * w.w;
        }
    }

    float4 bv = *(float4*)&Bs[tx * 4];
#pragma unroll
    for (int r = 0; r < 8; r++) {
        int gr = row0 + ty * 8 + r;
        if (gr < n) {
            float4 o = make_float4(acc[r][0] + bv.x, acc[r][1] + bv.y,
                                   acc[r][2] + bv.z, acc[r][3] + bv.w);
            *(float4*)&C[(size_t)gr * 128 + tx * 4] = o;
        }
    }
}

// ---------------- reparametrize epilogue -----------------------------------
__global__ void k_out(const float* __restrict__ T, const float* __restrict__ initd,
                      float* __restrict__ out, int n) {
    int idx = blockIdx.x * blockDim.x + threadIdx.x;
    if (idx >= n * OUTC) return;
    int i = idx >> 6, j = idx & 63;
    float mu = T[(size_t)i * 128 + j];
    float ls = T[(size_t)i * 128 + 64 + j];
    out[idx] = mu + initd[idx] * expf(ls);
}

// ---------------- launch ----------------------------------------------------
extern "C" void kernel_launch(void* const* d_in, const int* in_sizes, int n_in,
                              void* d_out, int out_size) {
    const float* x    = (const float*)d_in[0];
    const int*   ei   = (const int*)d_in[1];
    const float* initd= (const float*)d_in[2];
    const float* W1   = (const float*)d_in[3];
    const float* b1   = (const float*)d_in[4];
    const float* Wmu  = (const float*)d_in[5];
    const float* bmu  = (const float*)d_in[6];
    const float* Wls  = (const float*)d_in[7];
    const float* bls  = (const float*)d_in[8];
    float* out = (float*)d_out;

    int n = in_sizes[0] / FD;
    int e = in_sizes[1] / 2;

    void *pA = nullptr, *pB = nullptr;
    cudaGetSymbolAddress(&pA, g_bufA);
    cudaGetSymbolAddress(&pB, g_bufB);
    float* bufA = (float*)pA;
    float* bufB = (float*)pB;

    int gemm_smem = (128 * 128 + 64 * 128 + 128) * sizeof(float);
    cudaFuncSetAttribute(k_gemm, cudaFuncAttributeMaxDynamicSharedMemorySize, gemm_smem);

    // CSR build + degree
    k_zero_cnt<<<(n + 255) / 256, 256>>>(n);
    k_count<<<(e + 255) / 256, 256>>>(ei, e);
    int nb = (n + 1023) / 1024;
    k_scan1<<<nb, 256>>>(n);
    k_scan2<<<1, 256>>>(nb);
    k_final<<<(n + 255) / 256, 256>>>(n);
    k_fill<<<(e + 255) / 256, 256>>>(ei, e);

    int agg_grid = (n * 32 + 255) / 256;
    int gemm_grid = (n + 63) / 64;

    // layer 1: ax = A_norm x ; h = ax @ W1 + b1
    k_agg<<<agg_grid, 256>>>(x, bufA, n);
    k_gemm<<<gemm_grid, 256, gemm_smem>>>(bufA, W1, 128, W1, b1, b1, bufB, n);

    // layer 2: ah = A_norm h ; t = ah @ [Wmu|Wls] + [bmu|bls]
    k_agg<<<agg_grid, 256>>>(bufB, bufA, n);
    k_gemm<<<gemm_grid, 256, gemm_smem>>>(bufA, Wmu, 64, Wls, bmu, bls, bufB, n);

    // out = mu + init * exp(logstd)
    k_out<<<(n * OUTC + 255) / 256, 256>>>(bufB, initd, out, n);
}

// round 3
// speedup vs baseline: 1.5014x; 1.5014x over previous
#include <cuda_runtime.h>
#include <cuda_bf16.h>
#include <cstdint>
#include <math.h>

#define MAXN 100000
#define MAXE 1600000
#define FD   128      // IN == HID == 128
#define OUTC 64

// ---------------- scratch (device globals; no allocation allowed) ----------
__device__ float g_bufA[MAXN * FD];   // agg outputs
__device__ float g_bufB[MAXN * FD];   // gemm outputs
__device__ int   g_cnt[MAXN];
__device__ int   g_rowptr[MAXN + 1];
__device__ int   g_cursor[MAXN];
__device__ int   g_csr[MAXE];
__device__ float g_dinv[MAXN];
__device__ int   g_bsums[256];

// ---------------- degree / CSR build ---------------------------------------
__global__ void k_zero_cnt(int n) {
    int i = blockIdx.x * blockDim.x + threadIdx.x;
    if (i < n) g_cnt[i] = 0;
}

__global__ void k_count(const int* __restrict__ ei, int e) {
    int i = blockIdx.x * blockDim.x + threadIdx.x;
    if (i < e) atomicAdd(&g_cnt[ei[e + i]], 1);
}

__global__ void k_scan1(int n) {
    int tid = threadIdx.x, lane = tid & 31, w = tid >> 5;
    int base = blockIdx.x * 1024 + tid * 4;
    int v[4], inc[4];
    int s = 0;
#pragma unroll
    for (int j = 0; j < 4; j++) {
        v[j] = (base + j < n) ? g_cnt[base + j] : 0;
        s += v[j];
        inc[j] = s;
    }
    int x = s;
#pragma unroll
    for (int o = 1; o < 32; o <<= 1) {
        int t = __shfl_up_sync(0xFFFFFFFFu, x, o);
        if (lane >= o) x += t;
    }
    __shared__ int wsum[8], woff[8];
    if (lane == 31) wsum[w] = x;
    __syncthreads();
    if (tid < 8) {
        int ws = wsum[tid];
        int y = ws;
#pragma unroll
        for (int o = 1; o < 8; o <<= 1) {
            int t = __shfl_up_sync(0xFFu, y, o);
            if (tid >= o) y += t;
        }
        woff[tid] = y - ws;
        if (tid == 7) g_bsums[blockIdx.x] = y;
    }
    __syncthreads();
    int thread_excl = woff[w] + x - s;
#pragma unroll
    for (int j = 0; j < 4; j++)
        if (base + j < n) g_cursor[base + j] = thread_excl + inc[j];
}

__global__ void k_scan2(int nb) {
    int tid = threadIdx.x, lane = tid & 31, w = tid >> 5;
    int v = (tid < nb) ? g_bsums[tid] : 0;
    int x = v;
#pragma unroll
    for (int o = 1; o < 32; o <<= 1) {
        int t = __shfl_up_sync(0xFFFFFFFFu, x, o);
        if (lane >= o) x += t;
    }
    __shared__ int wsum[8], woff[8];
    if (lane == 31) wsum[w] = x;
    __syncthreads();
    if (tid < 8) {
        int ws = wsum[tid];
        int y = ws;
#pragma unroll
        for (int o = 1; o < 8; o <<= 1) {
            int t = __shfl_up_sync(0xFFu, y, o);
            if (tid >= o) y += t;
        }
        woff[tid] = y - ws;
    }
    __syncthreads();
    int incl = woff[w] + x;
    if (tid < nb) g_bsums[tid] = incl - v;
}

__global__ void k_final(int n) {
    int i = blockIdx.x * blockDim.x + threadIdx.x;
    if (i >= n) return;
    int incl = g_cursor[i] + g_bsums[i >> 10];
    int c = g_cnt[i];
    int excl = incl - c;
    g_rowptr[i] = excl;
    g_cursor[i] = excl;
    g_dinv[i] = rsqrtf((float)c + 1.0f);
    if (i == n - 1) g_rowptr[n] = incl;
}

__global__ void k_fill(const int* __restrict__ ei, int e) {
    int i = blockIdx.x * blockDim.x + threadIdx.x;
    if (i < e) {
        int d = ei[e + i];
        int p = atomicAdd(&g_cursor[d], 1);
        g_csr[p] = ei[i];
    }
}

// ---------------- normalized aggregation: Y = D^-1/2 (A+I) D^-1/2 X --------
__global__ void k_agg(const float* __restrict__ X, float* __restrict__ Y, int n) {
    int gw = (blockIdx.x * blockDim.x + threadIdx.x) >> 5;
    int lane = threadIdx.x & 31;
    if (gw >= n) return;
    float di = g_dinv[gw];
    const float4* x4 = (const float4*)X;

    float4 a = __ldg(&x4[(size_t)gw * 32 + lane]);
    float4 acc = make_float4(di * a.x, di * a.y, di * a.z, di * a.w);

    int s0 = g_rowptr[gw], s1 = g_rowptr[gw + 1];
    int e = s0;
    for (; e + 1 < s1; e += 2) {
        int sA = __ldg(&g_csr[e]);
        int sB = __ldg(&g_csr[e + 1]);
        float wA = __ldg(&g_dinv[sA]);
        float wB = __ldg(&g_dinv[sB]);
        float4 vA = __ldg(&x4[(size_t)sA * 32 + lane]);
        float4 vB = __ldg(&x4[(size_t)sB * 32 + lane]);
        acc.x += wA * vA.x + wB * vB.x;
        acc.y += wA * vA.y + wB * vB.y;
        acc.z += wA * vA.z + wB * vB.z;
        acc.w += wA * vA.w + wB * vB.w;
    }
    if (e < s1) {
        int sA = __ldg(&g_csr[e]);
        float wA = __ldg(&g_dinv[sA]);
        float4 vA = __ldg(&x4[(size_t)sA * 32 + lane]);
        acc.x += wA * vA.x; acc.y += wA * vA.y;
        acc.z += wA * vA.z; acc.w += wA * vA.w;
    }
    float4 o = make_float4(di * acc.x, di * acc.y, di * acc.z, di * acc.w);
    ((float4*)Y)[(size_t)gw * 32 + lane] = o;
}

// ================= mma.sync split-bf16 GEMM =================================
// C[n,128] = A[n,128] @ [Wa|Wb](128x128) + [ba|bb]
// A split to bf16 hi+lo; D = Ahi*Bhi + Ahi*Blo + Alo*Bhi, fp32 accumulate.
// CTA: 256 thr (8 warps), 128 rows; warp = 16-row strip.
// B (=W^T, [n][k]) in smem, stride 136 bf16 (ldmatrix conflict-free).

#define KS_B 136
#define SOFF_BH 0
#define SOFF_BL (128 * KS_B * 2)
#define SOFF_BIAS (SOFF_BL + 128 * KS_B * 2)
#define SMEM_MMA (SOFF_BIAS + 128 * 4)

__device__ __forceinline__ void split2(float a, float b, uint32_t& hi, uint32_t& lo) {
    __nv_bfloat16 ah = __float2bfloat16(a), bh = __float2bfloat16(b);
    float ar = a - __bfloat162float(ah);
    float br = b - __bfloat162float(bh);
    __nv_bfloat16 al = __float2bfloat16(ar), bl = __float2bfloat16(br);
    __nv_bfloat162 h; h.x = ah; h.y = bh;
    __nv_bfloat162 l; l.x = al; l.y = bl;
    hi = *(uint32_t*)&h;
    lo = *(uint32_t*)&l;
}

__device__ __forceinline__ uint32_t smem_u32(const void* p) {
    uint32_t a;
    asm("{ .reg .u64 t; cvta.to.shared.u64 t, %1; cvt.u32.u64 %0, t; }" : "=r"(a) : "l"(p));
    return a;
}

__device__ __forceinline__ void mma16816(float& c0, float& c1, float& c2, float& c3,
                                         uint32_t a0, uint32_t a1, uint32_t a2, uint32_t a3,
                                         uint32_t b0, uint32_t b1) {
    asm volatile(
        "mma.sync.aligned.m16n8k16.row.col.f32.bf16.bf16.f32 "
        "{%0,%1,%2,%3}, {%4,%5,%6,%7}, {%8,%9}, {%0,%1,%2,%3};"
        : "+f"(c0), "+f"(c1), "+f"(c2), "+f"(c3)
        : "r"(a0), "r"(a1), "r"(a2), "r"(a3), "r"(b0), "r"(b1));
}

__device__ __forceinline__ void ldsm_x2(uint32_t& r0, uint32_t& r1, uint32_t addr) {
    asm volatile("ldmatrix.sync.aligned.m8n8.x2.shared.b16 {%0, %1}, [%2];"
        : "=r"(r0), "=r"(r1) : "r"(addr));
}

__global__ void __launch_bounds__(256)
k_mma_gemm(const float* __restrict__ A,
           const float* __restrict__ Wa, int Na,
           const float* __restrict__ Wb,
           const float* __restrict__ ba, const float* __restrict__ bb,
           float* __restrict__ C, int n) {
    extern __shared__ char smem[];
    uint16_t* BH = (uint16_t*)(smem + SOFF_BH);
    uint16_t* BL = (uint16_t*)(smem + SOFF_BL);
    float*    Bs = (float*)(smem + SOFF_BIAS);
    int tid = threadIdx.x;
    int wid = tid >> 5, lane = tid & 31;
    int row0 = blockIdx.x * 128;
    int Nb = 128 - Na;

    // ---- B = W^T into smem (hi/lo), [n][k] padded stride 136 ---------------
    {
        int col = tid >> 1;                 // output column n (0..127)
        int kbeg = (tid & 1) * 64;
        const float* Wcol = (col < Na) ? (Wa + col) : (Wb + (col - Na));
        int stride = (col < Na) ? Na : Nb;
#pragma unroll 8
        for (int k = kbeg; k < kbeg + 64; k++) {
            float w = __ldg(&Wcol[k * stride]);
            __nv_bfloat16 wh = __float2bfloat16(w);
            float wr = w - __bfloat162float(wh);
            __nv_bfloat16 wl = __float2bfloat16(wr);
            BH[col * KS_B + k] = *(uint16_t*)&wh;
            BL[col * KS_B + k] = *(uint16_t*)&wl;
        }
    }
    if (tid < 128) Bs[tid] = (tid < Na) ? __ldg(&ba[tid]) : __ldg(&bb[tid - Na]);

    // ---- A fragments from gmem (split hi/lo into regs) ---------------------
    int rbase = row0 + wid * 16;
    int r0 = rbase + (lane >> 2);
    int r1 = r0 + 8;
    int r0c = (r0 < n) ? r0 : 0;
    int r1c = (r1 < n) ? r1 : 0;
    const float* A0 = A + (size_t)r0c * 128;
    const float* A1 = A + (size_t)r1c * 128;
    int cc = (lane & 3) * 2;

    uint32_t aH[8][4], aL[8][4];
#pragma unroll
    for (int ks = 0; ks < 8; ks++) {
        int k0 = ks * 16;
        float2 v00 = __ldg((const float2*)&A0[k0 + cc]);
        float2 v10 = __ldg((const float2*)&A1[k0 + cc]);
        float2 v02 = __ldg((const float2*)&A0[k0 + cc + 8]);
        float2 v12 = __ldg((const float2*)&A1[k0 + cc + 8]);
        split2(v00.x, v00.y, aH[ks][0], aL[ks][0]);
        split2(v10.x, v10.y, aH[ks][1], aL[ks][1]);
        split2(v02.x, v02.y, aH[ks][2], aL[ks][2]);
        split2(v12.x, v12.y, aH[ks][3], aL[ks][3]);
    }

    __syncthreads();

    // ldmatrix per-lane address pieces (lanes 0-15 meaningful for x2)
    uint32_t bh_base = smem_u32(BH);
    uint32_t bl_base = smem_u32(BL);
    uint32_t lrow = (uint32_t)(lane & 7);
    uint32_t khalf = ((uint32_t)(lane >> 3) & 1) * 8;

    bool w0 = (r0 < n), w1 = (r1 < n);
    float* C0 = C + (size_t)r0c * 128;
    float* C1 = C + (size_t)r1c * 128;

#pragma unroll 2
    for (int nb = 0; nb < 16; nb++) {
        int n0 = nb * 8;
        uint32_t off = ((n0 + lrow) * KS_B + khalf) * 2;
        uint32_t adH = bh_base + off;
        uint32_t adL = bl_base + off;
        float c0 = 0.f, c1 = 0.f, c2 = 0.f, c3 = 0.f;
#pragma unroll
        for (int ks = 0; ks < 8; ks++) {
            uint32_t bh0, bh1, bl0, bl1;
            ldsm_x2(bh0, bh1, adH + ks * 32);
            ldsm_x2(bl0, bl1, adL + ks * 32);
            mma16816(c0, c1, c2, c3, aH[ks][0], aH[ks][1], aH[ks][2], aH[ks][3], bh0, bh1);
            mma16816(c0, c1, c2, c3, aH[ks][0], aH[ks][1], aH[ks][2], aH[ks][3], bl0, bl1);
            mma16816(c0, c1, c2, c3, aL[ks][0], aL[ks][1], aL[ks][2], aL[ks][3], bh0, bh1);
        }
        float bx = Bs[n0 + cc], by = Bs[n0 + cc + 1];
        if (w0) *(float2*)&C0[n0 + cc] = make_float2(c0 + bx, c1 + by);
        if (w1) *(float2*)&C1[n0 + cc] = make_float2(c2 + bx, c3 + by);
    }
}

// ---------------- reparametrize epilogue -----------------------------------
__global__ void k_out(const float* __restrict__ T, const float* __restrict__ initd,
                      float* __restrict__ out, int n) {
    int idx = blockIdx.x * blockDim.x + threadIdx.x;
    if (idx >= n * OUTC) return;
    int i = idx >> 6, j = idx & 63;
    float mu = T[(size_t)i * 128 + j];
    float ls = T[(size_t)i * 128 + 64 + j];
    out[idx] = mu + initd[idx] * expf(ls);
}

// ---------------- launch ----------------------------------------------------
extern "C" void kernel_launch(void* const* d_in, const int* in_sizes, int n_in,
                              void* d_out, int out_size) {
    const float* x    = (const float*)d_in[0];
    const int*   ei   = (const int*)d_in[1];
    const float* initd= (const float*)d_in[2];
    const float* W1   = (const float*)d_in[3];
    const float* b1   = (const float*)d_in[4];
    const float* Wmu  = (const float*)d_in[5];
    const float* bmu  = (const float*)d_in[6];
    const float* Wls  = (const float*)d_in[7];
    const float* bls  = (const float*)d_in[8];
    float* out = (float*)d_out;

    int n = in_sizes[0] / FD;
    int e = in_sizes[1] / 2;

    void *pA = nullptr, *pB = nullptr;
    cudaGetSymbolAddress(&pA, g_bufA);
    cudaGetSymbolAddress(&pB, g_bufB);
    float* bufA = (float*)pA;
    float* bufB = (float*)pB;

    cudaFuncSetAttribute(k_mma_gemm, cudaFuncAttributeMaxDynamicSharedMemorySize, SMEM_MMA);

    // CSR build + degree
    k_zero_cnt<<<(n + 255) / 256, 256>>>(n);
    k_count<<<(e + 255) / 256, 256>>>(ei, e);
    int nb = (n + 1023) / 1024;
    k_scan1<<<nb, 256>>>(n);
    k_scan2<<<1, 256>>>(nb);
    k_final<<<(n + 255) / 256, 256>>>(n);
    k_fill<<<(e + 255) / 256, 256>>>(ei, e);

    int agg_grid = (n * 32 + 255) / 256;
    int gemm_grid = (n + 127) / 128;

    // layer 1: ax = A_norm x ; h = ax @ W1 + b1
    k_agg<<<agg_grid, 256>>>(x, bufA, n);
    k_mma_gemm<<<gemm_grid, 256, SMEM_MMA>>>(bufA, W1, 128, W1, b1, b1, bufB, n);

    // layer 2: ah = A_norm h ; t = ah @ [Wmu|Wls] + [bmu|bls]
    k_agg<<<agg_grid, 256>>>(bufB, bufA, n);
    k_mma_gemm<<<gemm_grid, 256, SMEM_MMA>>>(bufA, Wmu, 64, Wls, bmu, bls, bufB, n);

    // out = mu + init * exp(logstd)
    k_out<<<(n * OUTC + 255) / 256, 256>>>(bufB, initd, out, n);
}

// round 5
// speedup vs baseline: 1.8524x; 1.2338x over previous
#include <cuda_runtime.h>
#include <cuda_fp16.h>
#include <cuda_bf16.h>
#include <cstdint>
#include <math.h>

#define MAXN 100000
#define MAXE 1600000
#define FD   128      // IN == HID == 128
#define OUTC 64

// ---------------- scratch (device globals; no allocation allowed) ----------
__device__ __half g_bufH[MAXN * FD];  // fp16 GEMM outputs (U, then V)
__device__ float  g_bufA[MAXN * FD];  // fp32 h (layer-1 output)
__device__ int    g_cnt[MAXN];
__device__ int    g_rowptr[MAXN + 1];
__device__ int    g_cursor[MAXN];
__device__ int    g_csr[MAXE];
__device__ float  g_dinv[MAXN];
__device__ int    g_bsums[256];

// ---------------- degree / CSR build ---------------------------------------
__global__ void k_zero_cnt(int n) {
    int i = blockIdx.x * blockDim.x + threadIdx.x;
    if (i < n) g_cnt[i] = 0;
}

__global__ void k_count(const int* __restrict__ ei, int e) {
    int i = blockIdx.x * blockDim.x + threadIdx.x;
    if (i < e) atomicAdd(&g_cnt[ei[e + i]], 1);
}

__global__ void k_scan1(int n) {
    int tid = threadIdx.x, lane = tid & 31, w = tid >> 5;
    int base = blockIdx.x * 1024 + tid * 4;
    int v[4], inc[4];
    int s = 0;
#pragma unroll
    for (int j = 0; j < 4; j++) {
        v[j] = (base + j < n) ? g_cnt[base + j] : 0;
        s += v[j];
        inc[j] = s;
    }
    int x = s;
#pragma unroll
    for (int o = 1; o < 32; o <<= 1) {
        int t = __shfl_up_sync(0xFFFFFFFFu, x, o);
        if (lane >= o) x += t;
    }
    __shared__ int wsum[8], woff[8];
    if (lane == 31) wsum[w] = x;
    __syncthreads();
    if (tid < 8) {
        int ws = wsum[tid];
        int y = ws;
#pragma unroll
        for (int o = 1; o < 8; o <<= 1) {
            int t = __shfl_up_sync(0xFFu, y, o);
            if (tid >= o) y += t;
        }
        woff[tid] = y - ws;
        if (tid == 7) g_bsums[blockIdx.x] = y;
    }
    __syncthreads();
    int thread_excl = woff[w] + x - s;
#pragma unroll
    for (int j = 0; j < 4; j++)
        if (base + j < n) g_cursor[base + j] = thread_excl + inc[j];
}

__global__ void k_scan2(int nb) {
    int tid = threadIdx.x, lane = tid & 31, w = tid >> 5;
    int v = (tid < nb) ? g_bsums[tid] : 0;
    int x = v;
#pragma unroll
    for (int o = 1; o < 32; o <<= 1) {
        int t = __shfl_up_sync(0xFFFFFFFFu, x, o);
        if (lane >= o) x += t;
    }
    __shared__ int wsum[8], woff[8];
    if (lane == 31) wsum[w] = x;
    __syncthreads();
    if (tid < 8) {
        int ws = wsum[tid];
        int y = ws;
#pragma unroll
        for (int o = 1; o < 8; o <<= 1) {
            int t = __shfl_up_sync(0xFFu, y, o);
            if (tid >= o) y += t;
        }
        woff[tid] = y - ws;
    }
    __syncthreads();
    int incl = woff[w] + x;
    if (tid < nb) g_bsums[tid] = incl - v;
}

__global__ void k_final(int n) {
    int i = blockIdx.x * blockDim.x + threadIdx.x;
    if (i >= n) return;
    int incl = g_cursor[i] + g_bsums[i >> 10];
    int c = g_cnt[i];
    int excl = incl - c;
    g_rowptr[i] = excl;
    g_cursor[i] = excl;
    g_dinv[i] = rsqrtf((float)c + 1.0f);
    if (i == n - 1) g_rowptr[n] = incl;
}

__global__ void k_fill(const int* __restrict__ ei, int e) {
    int i = blockIdx.x * blockDim.x + threadIdx.x;
    if (i < e) {
        int d = ei[e + i];
        int p = atomicAdd(&g_cursor[d], 1);
        g_csr[p] = ei[i];
    }
}

// ---------------- fp16 gather core: acc = Sum dinv_s * row_s + dinv_d*self --
// one warp per node; lane handles 4 consecutive halves (uint2 = 8B).
__device__ __forceinline__ float4 agg_gather(const __half* __restrict__ X,
                                             int node, int lane, float di) {
    const uint2* x2 = (const uint2*)X;   // 32 uint2 per row
    uint2 sraw = __ldg(&x2[(size_t)node * 32 + lane]);
    __half2 s01 = *(__half2*)&sraw.x;
    __half2 s23 = *(__half2*)&sraw.y;
    float2 f01 = __half22float2(s01), f23 = __half22float2(s23);
    float4 acc = make_float4(di * f01.x, di * f01.y, di * f23.x, di * f23.y);

    int s0 = g_rowptr[node], s1 = g_rowptr[node + 1];
    int e = s0;
    for (; e + 1 < s1; e += 2) {
        int sA = __ldg(&g_csr[e]);
        int sB = __ldg(&g_csr[e + 1]);
        float wA = __ldg(&g_dinv[sA]);
        float wB = __ldg(&g_dinv[sB]);
        uint2 rA = __ldg(&x2[(size_t)sA * 32 + lane]);
        uint2 rB = __ldg(&x2[(size_t)sB * 32 + lane]);
        float2 a01 = __half22float2(*(__half2*)&rA.x);
        float2 a23 = __half22float2(*(__half2*)&rA.y);
        float2 b01 = __half22float2(*(__half2*)&rB.x);
        float2 b23 = __half22float2(*(__half2*)&rB.y);
        acc.x += wA * a01.x + wB * b01.x;
        acc.y += wA * a01.y + wB * b01.y;
        acc.z += wA * a23.x + wB * b23.x;
        acc.w += wA * a23.y + wB * b23.y;
    }
    if (e < s1) {
        int sA = __ldg(&g_csr[e]);
        float wA = __ldg(&g_dinv[sA]);
        uint2 rA = __ldg(&x2[(size_t)sA * 32 + lane]);
        float2 a01 = __half22float2(*(__half2*)&rA.x);
        float2 a23 = __half22float2(*(__half2*)&rA.y);
        acc.x += wA * a01.x; acc.y += wA * a01.y;
        acc.z += wA * a23.x; acc.w += wA * a23.y;
    }
    acc.x *= di; acc.y *= di; acc.z *= di; acc.w *= di;
    return acc;
}

// ---- agg1: h = Agg(U) + b1  (fp16 in, fp32 out) ----------------------------
__global__ void k_agg_bias(const __half* __restrict__ X, float* __restrict__ Y,
                           const float* __restrict__ bias, int n) {
    int gw = (blockIdx.x * blockDim.x + threadIdx.x) >> 5;
    int lane = threadIdx.x & 31;
    if (gw >= n) return;
    float di = g_dinv[gw];
    float4 acc = agg_gather(X, gw, lane, di);
    float4 b = __ldg((const float4*)&bias[lane * 4]);
    acc.x += b.x; acc.y += b.y; acc.z += b.z; acc.w += b.w;
    ((float4*)Y)[(size_t)gw * 32 + lane] = acc;
}

// ---- agg2: [mu|ls] = Agg(V)+bias; out = mu + init*exp(ls) ------------------
__global__ void k_agg_out(const __half* __restrict__ X,
                          const float* __restrict__ bmu, const float* __restrict__ bls,
                          const float* __restrict__ initd,
                          float* __restrict__ out, int n) {
    int gw = (blockIdx.x * blockDim.x + threadIdx.x) >> 5;
    int lane = threadIdx.x & 31;
    if (gw >= n) return;
    float di = g_dinv[gw];
    float4 v = agg_gather(X, gw, lane, di);
    // bias: cols 4*lane .. 4*lane+3 of [bmu|bls]
    float4 b = (lane < 16) ? __ldg((const float4*)&bmu[lane * 4])
                           : __ldg((const float4*)&bls[lane * 4 - 64]);
    v.x += b.x; v.y += b.y; v.z += b.z; v.w += b.w;
    // pair mu (lanes 0-15) with ls (lanes 16-31)
    float4 p;
    p.x = __shfl_xor_sync(0xFFFFFFFFu, v.x, 16);
    p.y = __shfl_xor_sync(0xFFFFFFFFu, v.y, 16);
    p.z = __shfl_xor_sync(0xFFFFFFFFu, v.z, 16);
    p.w = __shfl_xor_sync(0xFFFFFFFFu, v.w, 16);
    if (lane < 16) {
        float4 ini = __ldg((const float4*)&initd[(size_t)gw * 64 + lane * 4]);
        float4 o;
        o.x = v.x + ini.x * expf(p.x);
        o.y = v.y + ini.y * expf(p.y);
        o.z = v.z + ini.z * expf(p.z);
        o.w = v.w + ini.w * expf(p.w);
        *(float4*)&out[(size_t)gw * 64 + lane * 4] = o;
    }
}

// ================= mma.sync split-bf16 GEMM (fp16 out, no bias) =============
// C[n,128] = A[n,128] @ [Wa|Wb](128x128)
#define KS_B 136
#define SOFF_BH 0
#define SOFF_BL (128 * KS_B * 2)
#define SMEM_MMA (SOFF_BL + 128 * KS_B * 2)

__device__ __forceinline__ void split2(float a, float b, uint32_t& hi, uint32_t& lo) {
    __nv_bfloat16 ah = __float2bfloat16(a), bh = __float2bfloat16(b);
    float ar = a - __bfloat162float(ah);
    float br = b - __bfloat162float(bh);
    __nv_bfloat16 al = __float2bfloat16(ar), bl = __float2bfloat16(br);
    __nv_bfloat162 h; h.x = ah; h.y = bh;
    __nv_bfloat162 l; l.x = al; l.y = bl;
    hi = *(uint32_t*)&h;
    lo = *(uint32_t*)&l;
}

__device__ __forceinline__ uint32_t smem_u32(const void* p) {
    uint32_t a;
    asm("{ .reg .u64 t; cvta.to.shared.u64 t, %1; cvt.u32.u64 %0, t; }" : "=r"(a) : "l"(p));
    return a;
}

__device__ __forceinline__ void mma16816(float& c0, float& c1, float& c2, float& c3,
                                         uint32_t a0, uint32_t a1, uint32_t a2, uint32_t a3,
                                         uint32_t b0, uint32_t b1) {
    asm volatile(
        "mma.sync.aligned.m16n8k16.row.col.f32.bf16.bf16.f32 "
        "{%0,%1,%2,%3}, {%4,%5,%6,%7}, {%8,%9}, {%0,%1,%2,%3};"
        : "+f"(c0), "+f"(c1), "+f"(c2), "+f"(c3)
        : "r"(a0), "r"(a1), "r"(a2), "r"(a3), "r"(b0), "r"(b1));
}

__device__ __forceinline__ void ldsm_x2(uint32_t& r0, uint32_t& r1, uint32_t addr) {
    asm volatile("ldmatrix.sync.aligned.m8n8.x2.shared.b16 {%0, %1}, [%2];"
        : "=r"(r0), "=r"(r1) : "r"(addr));
}

__global__ void __launch_bounds__(256)
k_mma_gemm(const float* __restrict__ A,
           const float* __restrict__ Wa, int Na,
           const float* __restrict__ Wb,
           __half* __restrict__ C, int n) {
    extern __shared__ char smem[];
    uint16_t* BH = (uint16_t*)(smem + SOFF_BH);
    uint16_t* BL = (uint16_t*)(smem + SOFF_BL);
    int tid = threadIdx.x;
    int wid = tid >> 5, lane = tid & 31;
    int row0 = blockIdx.x * 128;
    int Nb = 128 - Na;

    // ---- B = W^T into smem (hi/lo), [n][k] padded stride 136 ---------------
    {
        int col = tid >> 1;
        int kbeg = (tid & 1) * 64;
        const float* Wcol = (col < Na) ? (Wa + col) : (Wb + (col - Na));
        int stride = (col < Na) ? Na : Nb;
#pragma unroll 8
        for (int k = kbeg; k < kbeg + 64; k++) {
            float w = __ldg(&Wcol[k * stride]);
            __nv_bfloat16 wh = __float2bfloat16(w);
            float wr = w - __bfloat162float(wh);
            __nv_bfloat16 wl = __float2bfloat16(wr);
            BH[col * KS_B + k] = *(uint16_t*)&wh;
            BL[col * KS_B + k] = *(uint16_t*)&wl;
        }
    }

    // ---- A fragments from gmem (split hi/lo into regs) ---------------------
    int rbase = row0 + wid * 16;
    int r0 = rbase + (lane >> 2);
    int r1 = r0 + 8;
    int r0c = (r0 < n) ? r0 : 0;
    int r1c = (r1 < n) ? r1 : 0;
    const float* A0 = A + (size_t)r0c * 128;
    const float* A1 = A + (size_t)r1c * 128;
    int cc = (lane & 3) * 2;

    uint32_t aH[8][4], aL[8][4];
#pragma unroll
    for (int ks = 0; ks < 8; ks++) {
        int k0 = ks * 16;
        float2 v00 = __ldg((const float2*)&A0[k0 + cc]);
        float2 v10 = __ldg((const float2*)&A1[k0 + cc]);
        float2 v02 = __ldg((const float2*)&A0[k0 + cc + 8]);
        float2 v12 = __ldg((const float2*)&A1[k0 + cc + 8]);
        split2(v00.x, v00.y, aH[ks][0], aL[ks][0]);
        split2(v10.x, v10.y, aH[ks][1], aL[ks][1]);
        split2(v02.x, v02.y, aH[ks][2], aL[ks][2]);
        split2(v12.x, v12.y, aH[ks][3], aL[ks][3]);
    }

    __syncthreads();

    uint32_t bh_base = smem_u32(BH);
    uint32_t bl_base = smem_u32(BL);
    uint32_t lrow = (uint32_t)(lane & 7);
    uint32_t khalf = ((uint32_t)(lane >> 3) & 1) * 8;

    bool w0 = (r0 < n), w1 = (r1 < n);
    __half* C0 = C + (size_t)r0c * 128;
    __half* C1 = C + (size_t)r1c * 128;

#pragma unroll 2
    for (int nb = 0; nb < 16; nb++) {
        int n0 = nb * 8;
        uint32_t off = ((n0 + lrow) * KS_B + khalf) * 2;
        uint32_t adH = bh_base + off;
        uint32_t adL = bl_base + off;
        float c0 = 0.f, c1 = 0.f, c2 = 0.f, c3 = 0.f;
#pragma unroll
        for (int ks = 0; ks < 8; ks++) {
            uint32_t bh0, bh1, bl0, bl1;
            ldsm_x2(bh0, bh1, adH + ks * 32);
            ldsm_x2(bl0, bl1, adL + ks * 32);
            mma16816(c0, c1, c2, c3, aH[ks][0], aH[ks][1], aH[ks][2], aH[ks][3], bh0, bh1);
            mma16816(c0, c1, c2, c3, aH[ks][0], aH[ks][1], aH[ks][2], aH[ks][3], bl0, bl1);
            mma16816(c0, c1, c2, c3, aL[ks][0], aL[ks][1], aL[ks][2], aL[ks][3], bh0, bh1);
        }
        if (w0) *(__half2*)&C0[n0 + cc] = __floats2half2_rn(c0, c1);
        if (w1) *(__half2*)&C1[n0 + cc] = __floats2half2_rn(c2, c3);
    }
}

// ---------------- launch ----------------------------------------------------
extern "C" void kernel_launch(void* const* d_in, const int* in_sizes, int n_in,
                              void* d_out, int out_size) {
    const float* x    = (const float*)d_in[0];
    const int*   ei   = (const int*)d_in[1];
    const float* initd= (const float*)d_in[2];
    const float* W1   = (const float*)d_in[3];
    const float* b1   = (const float*)d_in[4];
    const float* Wmu  = (const float*)d_in[5];
    const float* bmu  = (const float*)d_in[6];
    const float* Wls  = (const float*)d_in[7];
    const float* bls  = (const float*)d_in[8];
    float* out = (float*)d_out;

    int n = in_sizes[0] / FD;
    int e = in_sizes[1] / 2;

    void *pH = nullptr, *pA = nullptr;
    cudaGetSymbolAddress(&pH, g_bufH);
    cudaGetSymbolAddress(&pA, g_bufA);
    __half* bufH = (__half*)pH;
    float*  bufA = (float*)pA;

    cudaFuncSetAttribute(k_mma_gemm, cudaFuncAttributeMaxDynamicSharedMemorySize, SMEM_MMA);

    // CSR build + degree
    k_zero_cnt<<<(n + 255) / 256, 256>>>(n);
    k_count<<<(e + 255) / 256, 256>>>(ei, e);
    int nb = (n + 1023) / 1024;
    k_scan1<<<nb, 256>>>(n);
    k_scan2<<<1, 256>>>(nb);
    k_final<<<(n + 255) / 256, 256>>>(n);
    k_fill<<<(e + 255) / 256, 256>>>(ei, e);

    int agg_grid = (n * 32 + 255) / 256;
    int gemm_grid = (n + 127) / 128;

    // layer 1: U = x @ W1 (fp16) ; h = Agg(U) + b1 (fp32)
    k_mma_gemm<<<gemm_grid, 256, SMEM_MMA>>>(x, W1, 128, W1, bufH, n);
    k_agg_bias<<<agg_grid, 256>>>(bufH, bufA, b1, n);

    // layer 2: V = h @ [Wmu|Wls] (fp16) ; out = Agg(V)+bias, reparametrized
    k_mma_gemm<<<gemm_grid, 256, SMEM_MMA>>>(bufA, Wmu, 64, Wls, bufH, n);
    k_agg_out<<<agg_grid, 256>>>(bufH, bmu, bls, initd, out, n);
}